// round 1
// baseline (speedup 1.0000x reference)
#include <cuda_runtime.h>

#define FOV_TAN 0.57735026918962576451f   // tan(30 deg)
#define HALF    1.494140625f              // 255 * (3/256) * 0.5
#define NC      5                         // depth chunks
#define CSTEP   64                        // 320 / NC
#define NPIX    65536

// ---- scratch (no allocations allowed) ----
__device__ float g_cRGB[NC * NPIX];
__device__ float g_cT[NC * NPIX];
__device__ float g_gray[NPIX];
__device__ float g_psum[256], g_psq[256], g_pmin[256], g_pmax[256];
__device__ float g_scal[4];   // mean, sigma+eps, stdmin, denom

// ===========================================================================
// Kernel 1: ray-march one depth chunk per block. block = 256 threads (w = x),
// grid = (256 h, NC chunks). Stores per-chunk (rgb, transmittance).
// ===========================================================================
__global__ __launch_bounds__(256) void render_k(
    const float* __restrict__ vol,
    const float* __restrict__ camR,
    const float* __restrict__ camT)
{
    const int w = threadIdx.x;
    const int h = blockIdx.x;
    const int c = blockIdx.y;

    // linspace(-1, 1, 256)
    const float gx = __fadd_rn(-1.0f, __fmul_rn((float)w, 2.0f / 255.0f));
    const float gy = __fadd_rn(-1.0f, __fmul_rn((float)h, 2.0f / 255.0f));
    const float dcx = __fmul_rn(gx, FOV_TAN);
    const float dcy = __fmul_rn(gy, FOV_TAN);

    const float R0 = camR[0], R1 = camR[1], R2 = camR[2];
    const float R3 = camR[3], R4 = camR[4], R5 = camR[5];
    const float R6 = camR[6], R7 = camR[7], R8 = camR[8];
    const float T0 = camT[0], T1 = camT[1], T2 = camT[2];

    // origin = -R^T T ;  dir = R^T dirs_cam   (Rt[i][j] = R[j][i])
    const float ox = -(R0 * T0 + R3 * T1 + R6 * T2);
    const float oy = -(R1 * T0 + R4 * T1 + R7 * T2);
    const float oz = -(R2 * T0 + R5 * T1 + R8 * T2);
    const float dx = R0 * dcx + R3 * dcy + R6;
    const float dy = R1 * dcx + R4 * dcy + R7;
    const float dz = R2 * dcx + R5 * dcy + R8;

    float Tr  = 1.0f;
    float acc = 0.0f;
    const int p0 = c * CSTEP;

    #pragma unroll 4
    for (int i = 0; i < CSTEP; i++) {
        const int p = p0 + i;
        // linspace(2, 6, 320)
        const float d = __fadd_rn(2.0f, __fmul_rn((float)p, 4.0f / 319.0f));
        // local coords, op-order mirroring the reference (unfused)
        const float lx = __fdiv_rn(__fadd_rn(ox, __fmul_rn(dx, d)), HALF);
        const float ly = __fdiv_rn(__fadd_rn(oy, __fmul_rn(dy, d)), HALF);
        const float lz = __fdiv_rn(__fadd_rn(oz, __fmul_rn(dz, d)), HALF);

        const bool inside = (fabsf(lx) <= 1.0f) & (fabsf(ly) <= 1.0f) & (fabsf(lz) <= 1.0f);
        if (inside) {
            const float fx = __fmul_rn(__fmul_rn(__fadd_rn(lx, 1.0f), 0.5f), 255.0f);
            const float fy = __fmul_rn(__fmul_rn(__fadd_rn(ly, 1.0f), 0.5f), 255.0f);
            const float fz = __fmul_rn(__fmul_rn(__fadd_rn(lz, 1.0f), 0.5f), 255.0f);

            const float xf = floorf(fx), yf = floorf(fy), zf = floorf(fz);
            const float wx = fx - xf, wy = fy - yf, wz = fz - zf;
            const int x0 = (int)xf, y0 = (int)yf, z0 = (int)zf;  // in [0,255] when inside
            const int x1 = min(x0 + 1, 255);
            const int y1 = min(y0 + 1, 255);
            const int z1 = min(z0 + 1, 255);

            const float* b00 = vol + ((((z0 << 8) + y0) << 8));
            const float* b01 = vol + ((((z0 << 8) + y1) << 8));
            const float* b10 = vol + ((((z1 << 8) + y0) << 8));
            const float* b11 = vol + ((((z1 << 8) + y1) << 8));

            const float v000 = __ldg(b00 + x0), v001 = __ldg(b00 + x1);
            const float v010 = __ldg(b01 + x0), v011 = __ldg(b01 + x1);
            const float v100 = __ldg(b10 + x0), v101 = __ldg(b10 + x1);
            const float v110 = __ldg(b11 + x0), v111 = __ldg(b11 + x1);

            const float c00 = fmaf(wx, v001 - v000, v000);
            const float c01 = fmaf(wx, v011 - v010, v010);
            const float c10 = fmaf(wx, v101 - v100, v100);
            const float c11 = fmaf(wx, v111 - v110, v110);
            const float c0  = fmaf(wy, c01 - c00, c00);
            const float c1  = fmaf(wy, c11 - c10, c10);
            const float s   = fmaf(wz, c1 - c0, c0);

            // alpha = 0.1 exactly (constant density); 1-0.1+1e-10 -> 0.9f in fp32
            acc = fmaf(0.1f * Tr, s, acc);
            Tr *= 0.9f;
        }
        // outside: one_m = 1 + 1e-10 -> 1.0f in fp32: T unchanged
    }

    const int pix = (h << 8) + w;
    g_cRGB[c * NPIX + pix] = acc;
    g_cT[c * NPIX + pix]   = Tr;
}

// ===========================================================================
// Kernel 2: combine chunks front-to-back + block-level reduction partials
// ===========================================================================
__global__ __launch_bounds__(256) void combine_k()
{
    const int t   = threadIdx.x;
    const int pix = (blockIdx.x << 8) + t;

    float T = 1.0f, G = 0.0f;
    #pragma unroll
    for (int c = 0; c < NC; c++) {
        G = fmaf(T, g_cRGB[c * NPIX + pix], G);
        T *= g_cT[c * NPIX + pix];
    }
    g_gray[pix] = G;

    __shared__ float ssum[256], ssq[256], smin[256], smax[256];
    ssum[t] = G; ssq[t] = G * G; smin[t] = G; smax[t] = G;
    for (int o = 128; o > 0; o >>= 1) {
        __syncthreads();
        if (t < o) {
            ssum[t] += ssum[t + o];
            ssq[t]  += ssq[t + o];
            smin[t]  = fminf(smin[t], smin[t + o]);
            smax[t]  = fmaxf(smax[t], smax[t + o]);
        }
    }
    if (t == 0) {
        g_psum[blockIdx.x] = ssum[0];
        g_psq[blockIdx.x]  = ssq[0];
        g_pmin[blockIdx.x] = smin[0];
        g_pmax[blockIdx.x] = smax[0];
    }
}

// ===========================================================================
// Kernel 3: final 256-way reduction -> normalization scalars
// ===========================================================================
__global__ __launch_bounds__(256) void finalize_k()
{
    const int t = threadIdx.x;
    __shared__ double dsum[256], dsq[256];
    __shared__ float  fmn[256], fmx[256];
    dsum[t] = (double)g_psum[t];
    dsq[t]  = (double)g_psq[t];
    fmn[t]  = g_pmin[t];
    fmx[t]  = g_pmax[t];
    for (int o = 128; o > 0; o >>= 1) {
        __syncthreads();
        if (t < o) {
            dsum[t] += dsum[t + o];
            dsq[t]  += dsq[t + o];
            fmn[t]   = fminf(fmn[t], fmn[t + o]);
            fmx[t]   = fmaxf(fmx[t], fmx[t + o]);
        }
    }
    if (t == 0) {
        const double N = (double)NPIX;
        const double sum = dsum[0], sq = dsq[0];
        const double mean = sum / N;
        double var = (sq - sum * sum / N) / (N - 1.0);
        if (var < 0.0) var = 0.0;
        const float meanf = (float)mean;
        const float s     = (float)sqrt(var) + 1e-8f;     // sigma(ddof=1) + EPS
        const float stdmn = (fmn[0] - meanf) / s;
        const float stdmx = (fmx[0] - meanf) / s;
        g_scal[0] = meanf;
        g_scal[1] = s;
        g_scal[2] = stdmn;
        g_scal[3] = stdmx - stdmn + 1e-8f;                // denom
    }
}

// ===========================================================================
// Kernel 4: elementwise normalize + transpose into the output layout
// out[w*256 + h] = ((g[h*256+w]-mean)/s - stdmin + EPS) / denom
// ===========================================================================
__global__ __launch_bounds__(256) void norm_k(float* __restrict__ out)
{
    const int w = blockIdx.x;
    const int h = threadIdx.x;
    const float mean  = g_scal[0];
    const float s     = g_scal[1];
    const float stdmn = g_scal[2];
    const float denom = g_scal[3];
    const float g = g_gray[(h << 8) + w];
    const float stdv = (g - mean) / s;
    out[(w << 8) + h] = (stdv - stdmn + 1e-8f) / denom;
}

extern "C" void kernel_launch(void* const* d_in, const int* in_sizes, int n_in,
                              void* d_out, int out_size)
{
    const float* vol  = (const float*)d_in[0];   // image3d (1,1,256,256,256)
    const float* camR = (const float*)d_in[1];   // (1,3,3)
    const float* camT = (const float*)d_in[2];   // (1,3)
    float* out = (float*)d_out;                  // (1,1,256,256)

    render_k<<<dim3(256, NC), 256>>>(vol, camR, camT);
    combine_k<<<256, 256>>>();
    finalize_k<<<1, 256>>>();
    norm_k<<<256, 256>>>(out);
}